// round 2
// baseline (speedup 1.0000x reference)
#include <cuda_runtime.h>
#include <math.h>

// Problem constants
#define BDIM 64
#define TDIM 64
#define SDIM 128
#define HDIM 1024
#define EDIM 1024
#define VDIM 32000
#define G3H  3072          // 3*H
#define INPD 2048          // H + E

// ---------------- scratch (static device globals; no allocation) ----------------
__device__ float g_kproj[(size_t)BDIM * SDIM * HDIM];   // [B,S,H]   33.5 MB
__device__ float g_xs[(size_t)TDIM * BDIM * EDIM];      // [T,B,E]   16.8 MB
__device__ float g_h[2 * BDIM * HDIM];                  // [2,B,H]
__device__ float g_q[BDIM * HDIM];                      // [B,H]
__device__ float g_attn[BDIM * SDIM];                   // [B,S]
__device__ float g_inp[BDIM * INPD];                    // [B,H+E]
__device__ float g_gi0[BDIM * G3H];
__device__ float g_gh0[BDIM * G3H];
__device__ float g_gi1[BDIM * G3H];
__device__ float g_gh1[BDIM * G3H];
__device__ float g_ys[(size_t)TDIM * BDIM * HDIM];      // [T,B,H]   16.8 MB

// ---------------- helpers ----------------
__device__ __forceinline__ float fast_tanh(float x) {
    float y;
    asm("tanh.approx.f32 %0, %1;" : "=f"(y) : "f"(x));
    return y;
}
__device__ __forceinline__ float fast_sigmoid(float x) {
    return 1.0f / (1.0f + __expf(-x));
}
__device__ __forceinline__ float warpReduceSum(float v) {
    #pragma unroll
    for (int o = 16; o > 0; o >>= 1) v += __shfl_xor_sync(0xffffffffu, v, o);
    return v;
}
__device__ __forceinline__ float warpReduceMax(float v) {
    #pragma unroll
    for (int o = 16; o > 0; o >>= 1) v = fmaxf(v, __shfl_xor_sync(0xffffffffu, v, o));
    return v;
}

// ---------------- generic tiled SGEMM: C[M,N] = A[M,K] @ W[N,K]^T + bias ----------------
// A row-major lda=K, W row-major [N,K] (PyTorch-style weight), C row-major ldc=N.
// ROWMAP: output row r=t*B+b is stored at row (b*T+t)  (used for logits -> [B,T,V]).
// Requires: M % BM == 0, N % BN == 0, K % BK == 0 (all true for our fixed shapes).
template <int BM, int BN, int BK, int TM, int TN, bool ROWMAP>
__global__ __launch_bounds__((BM / TM) * (BN / TN))
void sgemm_bias(const float* __restrict__ A, const float* __restrict__ W,
                const float* __restrict__ bias, float* __restrict__ C,
                int M, int N, int K)
{
    constexpr int TX = BN / TN;
    constexpr int TY = BM / TM;
    constexpr int THREADS = TX * TY;

    __shared__ float As[BK][BM];
    __shared__ float Ws[BK][BN];

    const int bm = blockIdx.y * BM;
    const int bn = blockIdx.x * BN;
    const int tid = threadIdx.x;
    const int tx = tid % TX;
    const int ty = tid / TX;

    float acc[TM][TN];
    #pragma unroll
    for (int i = 0; i < TM; i++)
        #pragma unroll
        for (int j = 0; j < TN; j++) acc[i][j] = 0.0f;

    for (int k0 = 0; k0 < K; k0 += BK) {
        constexpr int AV = BM * BK / 4;   // float4 vectors in A tile
        #pragma unroll
        for (int v = tid; v < AV; v += THREADS) {
            int row = v / (BK / 4);
            int c4  = v % (BK / 4);
            float4 f = *reinterpret_cast<const float4*>(
                &A[(size_t)(bm + row) * K + k0 + c4 * 4]);
            As[c4 * 4 + 0][row] = f.x;
            As[c4 * 4 + 1][row] = f.y;
            As[c4 * 4 + 2][row] = f.z;
            As[c4 * 4 + 3][row] = f.w;
        }
        constexpr int WV = BN * BK / 4;
        #pragma unroll
        for (int v = tid; v < WV; v += THREADS) {
            int row = v / (BK / 4);
            int c4  = v % (BK / 4);
            float4 f = *reinterpret_cast<const float4*>(
                &W[(size_t)(bn + row) * K + k0 + c4 * 4]);
            Ws[c4 * 4 + 0][row] = f.x;
            Ws[c4 * 4 + 1][row] = f.y;
            Ws[c4 * 4 + 2][row] = f.z;
            Ws[c4 * 4 + 3][row] = f.w;
        }
        __syncthreads();

        #pragma unroll
        for (int k = 0; k < BK; k++) {
            float a[TM], b[TN];
            #pragma unroll
            for (int i = 0; i < TM; i++) a[i] = As[k][ty * TM + i];
            #pragma unroll
            for (int j = 0; j < TN; j++) b[j] = Ws[k][tx * TN + j];
            #pragma unroll
            for (int i = 0; i < TM; i++)
                #pragma unroll
                for (int j = 0; j < TN; j++)
                    acc[i][j] = fmaf(a[i], b[j], acc[i][j]);
        }
        __syncthreads();
    }

    #pragma unroll
    for (int i = 0; i < TM; i++) {
        int r = bm + ty * TM + i;
        size_t rowBase;
        if (ROWMAP) {
            // r = t*BDIM + b  ->  out row = b*TDIM + t   (B==T==64)
            int b = r & (BDIM - 1);
            int t = r >> 6;
            rowBase = (size_t)(b * TDIM + t) * N;
        } else {
            rowBase = (size_t)r * N;
        }
        #pragma unroll
        for (int j = 0; j < TN; j++) {
            int c = bn + tx * TN + j;
            float v = acc[i][j];
            if (bias) v += bias[c];
            C[rowBase + c] = v;
        }
    }
}

// ---------------- embedding gather: xs[T,B,E] = table[X[b,t]] ----------------
__global__ void gather_kernel(const int* __restrict__ X, const float* __restrict__ table)
{
    size_t i = (size_t)blockIdx.x * blockDim.x + threadIdx.x;
    if (i >= (size_t)TDIM * BDIM * EDIM) return;
    int e = (int)(i % EDIM);
    size_t tb = i / EDIM;
    int b = (int)(tb % BDIM);
    int t = (int)(tb / BDIM);
    g_xs[i] = table[(size_t)X[b * TDIM + t] * EDIM + e];
}

// ---------------- attention scores: scores[b,s] = sum_h tanh(q+kproj)*wv + bv ----------------
__global__ void attn_scores_kernel(const float* __restrict__ q,
                                   const float* __restrict__ wv,
                                   const float* __restrict__ bv)
{
    const int s = blockIdx.x;
    const int b = blockIdx.y;
    const float* kp = &g_kproj[((size_t)b * SDIM + s) * HDIM];
    const float* qb = &q[b * HDIM];

    float sum = 0.0f;
    for (int h = threadIdx.x; h < HDIM; h += 128)
        sum += fast_tanh(qb[h] + kp[h]) * wv[h];

    sum = warpReduceSum(sum);
    __shared__ float sh[4];
    if ((threadIdx.x & 31) == 0) sh[threadIdx.x >> 5] = sum;
    __syncthreads();
    if (threadIdx.x == 0)
        g_attn[b * SDIM + s] = sh[0] + sh[1] + sh[2] + sh[3] + bv[0];
}

// ---------------- softmax over S=128 (one block per b, 128 threads) ----------------
__global__ void softmax_kernel()
{
    const int b = blockIdx.x;
    const int t = threadIdx.x;
    float v = g_attn[b * SDIM + t];

    float m = warpReduceMax(v);
    __shared__ float shm[4], shs[4];
    if ((t & 31) == 0) shm[t >> 5] = m;
    __syncthreads();
    m = fmaxf(fmaxf(shm[0], shm[1]), fmaxf(shm[2], shm[3]));

    float e = __expf(v - m);
    float s = warpReduceSum(e);
    if ((t & 31) == 0) shs[t >> 5] = s;
    __syncthreads();
    float tot = shs[0] + shs[1] + shs[2] + shs[3];

    g_attn[b * SDIM + t] = e / tot;
}

// ---------------- ctx + pack input: inp[b, :H] = attn @ enc_Y ; inp[b, H:] = xs[t,b] ----------------
// grid (8, B): blocks 0..3 compute ctx (h chunk of 256), blocks 4..7 copy the embedding.
__global__ void ctx_pack_kernel(const float* __restrict__ encY, int t)
{
    const int b = blockIdx.y;
    if (blockIdx.x < 4) {
        __shared__ float at[SDIM];
        if (threadIdx.x < SDIM) at[threadIdx.x] = g_attn[b * SDIM + threadIdx.x];
        __syncthreads();
        const int h = blockIdx.x * 256 + threadIdx.x;
        const float* ey = &encY[(size_t)b * SDIM * HDIM + h];
        float acc = 0.0f;
        #pragma unroll 8
        for (int s = 0; s < SDIM; s++)
            acc = fmaf(at[s], ey[(size_t)s * HDIM], acc);
        g_inp[b * INPD + h] = acc;
    } else {
        const int e = (blockIdx.x - 4) * 256 + threadIdx.x;
        g_inp[b * INPD + HDIM + e] = g_xs[((size_t)t * BDIM + b) * EDIM + e];
    }
}

// ---------------- GRU gate combine (biases already folded into gi/gh via GEMM) ----------------
// h updated in place (elementwise same index is safe); optionally also writes ys.
__global__ void gru_gate_kernel(const float* __restrict__ gi, const float* __restrict__ gh,
                                float* __restrict__ h, float* __restrict__ ysout)
{
    const int i = blockIdx.x * blockDim.x + threadIdx.x;   // [0, B*H)
    const int b = i >> 10;
    const int j = i & (HDIM - 1);
    const float* gib = gi + (size_t)b * G3H;
    const float* ghb = gh + (size_t)b * G3H;

    float r = fast_sigmoid(gib[j] + ghb[j]);
    float z = fast_sigmoid(gib[HDIM + j] + ghb[HDIM + j]);
    float n = fast_tanh(gib[2 * HDIM + j] + r * ghb[2 * HDIM + j]);
    float hn = (1.0f - z) * n + z * h[i];
    h[i] = hn;
    if (ysout) ysout[i] = hn;
}

// ---------------- in-place log-softmax over V per output row ----------------
__global__ void logsoftmax_kernel(float* __restrict__ out)
{
    float* p = out + (size_t)blockIdx.x * VDIM;
    const int tid = threadIdx.x;

    float m = -1e30f;
    for (int v = tid; v < VDIM; v += 256) m = fmaxf(m, p[v]);
    m = warpReduceMax(m);
    __shared__ float shm[8];
    if ((tid & 31) == 0) shm[tid >> 5] = m;
    __syncthreads();
    m = shm[0];
    #pragma unroll
    for (int w = 1; w < 8; w++) m = fmaxf(m, shm[w]);

    float s = 0.0f;
    for (int v = tid; v < VDIM; v += 256) s += __expf(p[v] - m);
    s = warpReduceSum(s);
    __shared__ float shs[8];
    if ((tid & 31) == 0) shs[tid >> 5] = s;
    __syncthreads();
    s = shs[0];
    #pragma unroll
    for (int w = 1; w < 8; w++) s += shs[w];

    const float lse = m + logf(s);
    for (int v = tid; v < VDIM; v += 256) p[v] = p[v] - lse;
}

// ---------------- launcher ----------------
extern "C" void kernel_launch(void* const* d_in, const int* in_sizes, int n_in,
                              void* d_out, int out_size)
{
    (void)in_sizes; (void)n_in; (void)out_size;

    const int*   X     = (const int*)d_in[0];
    const float* encY  = (const float*)d_in[1];
    const float* h0in  = (const float*)d_in[2];
    const float* table = (const float*)d_in[3];
    const float* Wq    = (const float*)d_in[4];
    const float* bq    = (const float*)d_in[5];
    const float* Wk    = (const float*)d_in[6];
    const float* bk    = (const float*)d_in[7];
    const float* wv    = (const float*)d_in[8];
    const float* bv    = (const float*)d_in[9];
    const float* Wih0  = (const float*)d_in[10];
    const float* Whh0  = (const float*)d_in[11];
    const float* bih0  = (const float*)d_in[12];
    const float* bhh0  = (const float*)d_in[13];
    const float* Wih1  = (const float*)d_in[14];
    const float* Whh1  = (const float*)d_in[15];
    const float* bih1  = (const float*)d_in[16];
    const float* bhh1  = (const float*)d_in[17];
    const float* Wout  = (const float*)d_in[18];
    const float* bout  = (const float*)d_in[19];
    float* out = (float*)d_out;

    float *kproj, *h, *q, *inp, *gi0, *gh0, *gi1, *gh1, *ys;
    cudaGetSymbolAddress((void**)&kproj, g_kproj);
    cudaGetSymbolAddress((void**)&h,     g_h);
    cudaGetSymbolAddress((void**)&q,     g_q);
    cudaGetSymbolAddress((void**)&inp,   g_inp);
    cudaGetSymbolAddress((void**)&gi0,   g_gi0);
    cudaGetSymbolAddress((void**)&gh0,   g_gh0);
    cudaGetSymbolAddress((void**)&gi1,   g_gi1);
    cudaGetSymbolAddress((void**)&gh1,   g_gh1);
    cudaGetSymbolAddress((void**)&ys,    g_ys);

    // ---- prologue ----
    {
        size_t n = (size_t)TDIM * BDIM * EDIM;
        gather_kernel<<<(unsigned)((n + 255) / 256), 256>>>(X, table);
    }
    // kproj[B*S, H] = enc_Y @ Wk^T + bk
    sgemm_bias<64, 64, 16, 4, 4, false>
        <<<dim3(HDIM / 64, (BDIM * SDIM) / 64), 256>>>(encY, Wk, bk, kproj,
                                                       BDIM * SDIM, HDIM, HDIM);
    cudaMemcpyAsync(h, h0in, (size_t)2 * BDIM * HDIM * sizeof(float),
                    cudaMemcpyDeviceToDevice);

    float* h0p = h;                   // layer 0 hidden [B,H]
    float* h1p = h + BDIM * HDIM;     // layer 1 hidden [B,H]

    // ---- recurrent scan over T steps ----
    for (int t = 0; t < TDIM; t++) {
        // q = h1 @ Wq^T + bq
        sgemm_bias<64, 32, 16, 4, 2, false>
            <<<dim3(HDIM / 32, 1), 256>>>(h1p, Wq, bq, q, BDIM, HDIM, HDIM);
        // scores + softmax
        attn_scores_kernel<<<dim3(SDIM, BDIM), 128>>>(q, wv, bv);
        softmax_kernel<<<BDIM, 128>>>();
        // ctx into inp[:, :H], embedding into inp[:, H:]
        ctx_pack_kernel<<<dim3(8, BDIM), 256>>>(encY, t);
        // GRU layer 0
        sgemm_bias<64, 32, 16, 4, 2, false>
            <<<dim3(G3H / 32, 1), 256>>>(inp, Wih0, bih0, gi0, BDIM, G3H, INPD);
        sgemm_bias<64, 32, 16, 4, 2, false>
            <<<dim3(G3H / 32, 1), 256>>>(h0p, Whh0, bhh0, gh0, BDIM, G3H, HDIM);
        gru_gate_kernel<<<(BDIM * HDIM) / 256, 256>>>(gi0, gh0, h0p, nullptr);
        // GRU layer 1 (gh1 consumes OLD h1; launched before gate1 updates it)
        sgemm_bias<64, 32, 16, 4, 2, false>
            <<<dim3(G3H / 32, 1), 256>>>(h0p, Wih1, bih1, gi1, BDIM, G3H, HDIM);
        sgemm_bias<64, 32, 16, 4, 2, false>
            <<<dim3(G3H / 32, 1), 256>>>(h1p, Whh1, bhh1, gh1, BDIM, G3H, HDIM);
        gru_gate_kernel<<<(BDIM * HDIM) / 256, 256>>>(gi1, gh1, h1p,
                                                      ys + (size_t)t * BDIM * HDIM);
    }

    // ---- logits + log-softmax ----
    // logits[b,t,:] = ys[t,b,:] @ Wout^T + bout  (row permutation in the store)
    sgemm_bias<64, 64, 16, 4, 4, true>
        <<<dim3(VDIM / 64, (TDIM * BDIM) / 64), 256>>>(ys, Wout, bout, out,
                                                       TDIM * BDIM, VDIM, HDIM);
    logsoftmax_kernel<<<BDIM * TDIM, 256>>>(out);
}

// round 3
// speedup vs baseline: 2.2172x; 2.2172x over previous
#include <cuda_runtime.h>
#include <cuda_bf16.h>
#include <math.h>

// Problem constants
#define BDIM 64
#define TDIM 64
#define SDIM 128
#define HDIM 1024
#define EDIM 1024
#define VDIM 32000
#define G3H  3072          // 3*H
#define QGH  4096          // q(1024) | gh1(3072)

typedef __nv_bfloat16 bf16;

// ---------------- scratch (static device globals; no allocation) ----------------
__device__ bf16  g_kprojb[(size_t)BDIM * SDIM * HDIM];   // [B,S,H] bf16  16.8MB
__device__ bf16  g_encYb [(size_t)BDIM * SDIM * HDIM];   // 16.8MB
__device__ bf16  g_xsb   [(size_t)TDIM * BDIM * EDIM];   // [T*B, E]  8.4MB
__device__ bf16  g_Wihxb [G3H * HDIM];                   // Wih0[:,H:] bf16
__device__ bf16  g_Wkb   [HDIM * HDIM];
__device__ bf16  g_Woutb [(size_t)VDIM * HDIM];          // 65.5MB
__device__ bf16  g_ysb   [(size_t)TDIM * BDIM * HDIM];   // 8.4MB
__device__ float g_Xg    [(size_t)TDIM * BDIM * G3H];    // precomputed x-part of gi0 (+bih0)  50MB
__device__ float g_Wcat  [QGH * HDIM];                   // [Wq; Whh1]
__device__ float g_bcat  [QGH];
__device__ float g_h     [2 * BDIM * HDIM];
__device__ float g_qgh1  [BDIM * QGH];                   // per-row: q | gh1
__device__ float g_attn  [BDIM * SDIM];
__device__ float g_ctx   [BDIM * HDIM];
__device__ float g_gh0   [BDIM * G3H];
__device__ float g_gi0   [BDIM * G3H];
__device__ float g_gi1   [BDIM * G3H];

// ---------------- helpers ----------------
__device__ __forceinline__ float fast_tanh(float x) {
    float y;
    asm("tanh.approx.f32 %0, %1;" : "=f"(y) : "f"(x));
    return y;
}
__device__ __forceinline__ float fast_sigmoid(float x) {
    return 1.0f / (1.0f + __expf(-x));
}
__device__ __forceinline__ float warpReduceSum(float v) {
    #pragma unroll
    for (int o = 16; o > 0; o >>= 1) v += __shfl_xor_sync(0xffffffffu, v, o);
    return v;
}
__device__ __forceinline__ float warpReduceMax(float v) {
    #pragma unroll
    for (int o = 16; o > 0; o >>= 1) v = fmaxf(v, __shfl_xor_sync(0xffffffffu, v, o));
    return v;
}

__device__ __forceinline__ void mma16816(float* d, const unsigned* a, const unsigned* b) {
    asm volatile(
        "mma.sync.aligned.m16n8k16.row.col.f32.bf16.bf16.f32 "
        "{%0,%1,%2,%3},{%4,%5,%6,%7},{%8,%9},{%0,%1,%2,%3};"
        : "+f"(d[0]), "+f"(d[1]), "+f"(d[2]), "+f"(d[3])
        : "r"(a[0]), "r"(a[1]), "r"(a[2]), "r"(a[3]), "r"(b[0]), "r"(b[1]));
}

template <typename T> __device__ __forceinline__ T toOut(float v);
template <> __device__ __forceinline__ float toOut<float>(float v) { return v; }
template <> __device__ __forceinline__ bf16  toOut<bf16 >(float v) { return __float2bfloat16(v); }

// ============ bf16 tensor-core GEMM: C[M,N] = A[M,K] @ B[N,K]^T + bias ============
// A row-major [M,K] bf16 (lda=K), B row-major [N,K] bf16 (PyTorch weight layout ==
// col-major K x N for mma), C row-major [M,N] OutT.
// ROWMAP: output row g = t*64+b is stored at row b*64+t (logits -> [B,T,V]).
// Requires M%128==0, N%128==0, K%32==0.
template <typename OutT, bool ROWMAP>
__global__ __launch_bounds__(256)
void mma_gemm(const bf16* __restrict__ A, const bf16* __restrict__ B,
              const float* __restrict__ bias, OutT* __restrict__ C,
              int M, int N, int K)
{
    constexpr int BM = 128, BN = 128, BK = 32, PAD = 8;
    __shared__ bf16 As[BM][BK + PAD];
    __shared__ bf16 Bs[BN][BK + PAD];

    const int bm = blockIdx.y * BM;
    const int bn = blockIdx.x * BN;
    const int tid = threadIdx.x;
    const int lane = tid & 31;
    const int warp = tid >> 5;
    const int wm = (warp >> 2) * 64;   // warp M origin within tile (0 or 64)
    const int wn = (warp & 3) * 32;    // warp N origin within tile

    float acc[4][4][4];
    #pragma unroll
    for (int i = 0; i < 4; i++)
        #pragma unroll
        for (int j = 0; j < 4; j++)
            #pragma unroll
            for (int x = 0; x < 4; x++) acc[i][j][x] = 0.0f;

    const int r  = lane >> 2;          // 0..7
    const int c2 = (lane & 3) * 2;     // 0,2,4,6

    for (int k0 = 0; k0 < K; k0 += BK) {
        // cooperative tile load: 512 uint4 vectors per matrix / 256 threads
        #pragma unroll
        for (int v = 0; v < 2; v++) {
            int idx = tid + v * 256;        // 0..511
            int row = idx >> 2;             // 0..127
            int c8  = (idx & 3) * 8;        // 0,8,16,24
            *reinterpret_cast<uint4*>(&As[row][c8]) =
                *reinterpret_cast<const uint4*>(&A[(size_t)(bm + row) * K + k0 + c8]);
            *reinterpret_cast<uint4*>(&Bs[row][c8]) =
                *reinterpret_cast<const uint4*>(&B[(size_t)(bn + row) * K + k0 + c8]);
        }
        __syncthreads();

        #pragma unroll
        for (int ks = 0; ks < 2; ks++) {
            unsigned a[4][4], b[4][2];
            #pragma unroll
            for (int i = 0; i < 4; i++) {
                int mr = wm + i * 16;
                a[i][0] = *reinterpret_cast<const unsigned*>(&As[mr + r    ][ks * 16 + c2    ]);
                a[i][1] = *reinterpret_cast<const unsigned*>(&As[mr + r + 8][ks * 16 + c2    ]);
                a[i][2] = *reinterpret_cast<const unsigned*>(&As[mr + r    ][ks * 16 + c2 + 8]);
                a[i][3] = *reinterpret_cast<const unsigned*>(&As[mr + r + 8][ks * 16 + c2 + 8]);
            }
            #pragma unroll
            for (int j = 0; j < 4; j++) {
                int nr = wn + j * 8 + r;
                b[j][0] = *reinterpret_cast<const unsigned*>(&Bs[nr][ks * 16 + c2    ]);
                b[j][1] = *reinterpret_cast<const unsigned*>(&Bs[nr][ks * 16 + c2 + 8]);
            }
            #pragma unroll
            for (int i = 0; i < 4; i++)
                #pragma unroll
                for (int j = 0; j < 4; j++)
                    mma16816(acc[i][j], a[i], b[j]);
        }
        __syncthreads();
    }

    // epilogue
    #pragma unroll
    for (int i = 0; i < 4; i++) {
        int grow0 = bm + wm + i * 16 + r;
        #pragma unroll
        for (int half = 0; half < 2; half++) {
            int g = grow0 + half * 8;
            size_t rowBase;
            if (ROWMAP) {
                int b_ = g & (BDIM - 1);
                int t_ = g >> 6;
                rowBase = (size_t)(b_ * TDIM + t_) * N;
            } else {
                rowBase = (size_t)g * N;
            }
            #pragma unroll
            for (int j = 0; j < 4; j++) {
                int col = bn + wn + j * 8 + c2;
                float b0 = bias ? bias[col]     : 0.0f;
                float b1 = bias ? bias[col + 1] : 0.0f;
                C[rowBase + col    ] = toOut<OutT>(acc[i][j][half * 2    ] + b0);
                C[rowBase + col + 1] = toOut<OutT>(acc[i][j][half * 2 + 1] + b1);
            }
        }
    }
}

// ============ small fp32 SIMT GEMM for the recurrence: C[64,N] = A[64,K] @ W^T ============
// W row-major [N, ldw] (reads first K of each row). Optional bias[N] and addend P[64, ldp].
// BM=64, TM=4, BK=16. BN=32, TN=2 -> 256 threads.
template <int BN, int TN>
__device__ __forceinline__ void sgemm64_body(
    const float* __restrict__ A, const float* __restrict__ W, int ldw,
    const float* __restrict__ bias, const float* __restrict__ P, int ldp,
    float* __restrict__ C, int ldc, int bn, int K)
{
    constexpr int BM = 64, BK = 16, TM = 4;
    constexpr int TX = BN / TN;          // 16
    constexpr int TY = BM / TM;          // 16
    constexpr int THREADS = TX * TY;     // 256

    __shared__ float As[BK][BM];
    __shared__ float Ws[BK][BN];

    const int tid = threadIdx.x;
    const int tx = tid % TX;
    const int ty = tid / TX;

    float acc[TM][TN];
    #pragma unroll
    for (int i = 0; i < TM; i++)
        #pragma unroll
        for (int j = 0; j < TN; j++) acc[i][j] = 0.0f;

    for (int k0 = 0; k0 < K; k0 += BK) {
        constexpr int AV = BM * BK / 4;   // 256
        #pragma unroll
        for (int v = tid; v < AV; v += THREADS) {
            int row = v / (BK / 4);
            int c4  = v % (BK / 4);
            float4 f = *reinterpret_cast<const float4*>(&A[(size_t)row * K + k0 + c4 * 4]);
            As[c4 * 4 + 0][row] = f.x;
            As[c4 * 4 + 1][row] = f.y;
            As[c4 * 4 + 2][row] = f.z;
            As[c4 * 4 + 3][row] = f.w;
        }
        constexpr int WV = BN * BK / 4;
        #pragma unroll
        for (int v = tid; v < WV; v += THREADS) {
            int row = v / (BK / 4);
            int c4  = v % (BK / 4);
            float4 f = *reinterpret_cast<const float4*>(&W[(size_t)(bn + row) * ldw + k0 + c4 * 4]);
            Ws[c4 * 4 + 0][row] = f.x;
            Ws[c4 * 4 + 1][row] = f.y;
            Ws[c4 * 4 + 2][row] = f.z;
            Ws[c4 * 4 + 3][row] = f.w;
        }
        __syncthreads();

        #pragma unroll
        for (int k = 0; k < BK; k++) {
            float a[TM], b[TN];
            #pragma unroll
            for (int i = 0; i < TM; i++) a[i] = As[k][ty * TM + i];
            #pragma unroll
            for (int j = 0; j < TN; j++) b[j] = Ws[k][tx * TN + j];
            #pragma unroll
            for (int i = 0; i < TM; i++)
                #pragma unroll
                for (int j = 0; j < TN; j++)
                    acc[i][j] = fmaf(a[i], b[j], acc[i][j]);
        }
        __syncthreads();
    }

    #pragma unroll
    for (int i = 0; i < TM; i++) {
        int rr = ty * TM + i;
        #pragma unroll
        for (int j = 0; j < TN; j++) {
            int c = bn + tx * TN + j;
            float v = acc[i][j];
            if (bias) v += bias[c];
            if (P)    v += P[(size_t)rr * ldp + c];
            C[(size_t)rr * ldc + c] = v;
        }
    }
}

// generic single-GEMM wrapper
__global__ __launch_bounds__(256)
void sgemm_step(const float* __restrict__ A, const float* __restrict__ W, int ldw,
                const float* __restrict__ bias, const float* __restrict__ P, int ldp,
                float* __restrict__ C, int ldc, int K)
{
    sgemm64_body<32, 2>(A, W, ldw, bias, P, ldp, C, ldc, blockIdx.x * 32, K);
}

// fused step-start: [q|gh1] = h1 @ Wcat^T + bcat  (128 blocks)  +  gh0 = h0 @ Whh0^T + bhh0 (96)
__global__ __launch_bounds__(256)
void stepstart_gemm(const float* __restrict__ h1, const float* __restrict__ h0,
                    const float* __restrict__ Whh0, const float* __restrict__ bhh0)
{
    if (blockIdx.x < QGH / 32) {
        sgemm64_body<32, 2>(h1, g_Wcat, HDIM, g_bcat, nullptr, 0,
                            g_qgh1, QGH, blockIdx.x * 32, HDIM);
    } else {
        sgemm64_body<32, 2>(h0, Whh0, HDIM, bhh0, nullptr, 0,
                            g_gh0, G3H, (blockIdx.x - QGH / 32) * 32, HDIM);
    }
}

// ---------------- embedding gather -> bf16, row = t*64+b ----------------
__global__ void gather_kernel(const int* __restrict__ X, const float* __restrict__ table)
{
    size_t i = (size_t)blockIdx.x * blockDim.x + threadIdx.x;
    if (i >= (size_t)TDIM * BDIM * EDIM) return;
    int e = (int)(i % EDIM);
    size_t tb = i / EDIM;
    int b = (int)(tb % BDIM);
    int t = (int)(tb / BDIM);
    g_xsb[i] = __float2bfloat16(table[(size_t)X[b * TDIM + t] * EDIM + e]);
}

// ---------------- fp32 -> bf16 converters ----------------
__global__ void f2bf_kernel(const float* __restrict__ src, bf16* __restrict__ dst, size_t n)
{
    size_t i = (size_t)blockIdx.x * blockDim.x + threadIdx.x;
    if (i < n) dst[i] = __float2bfloat16(src[i]);
}
// dst[r*cols + c] = src[r*srcld + srcoff + c]
__global__ void f2bf_strided_kernel(const float* __restrict__ src, int srcld, int srcoff,
                                    bf16* __restrict__ dst, int rows, int cols)
{
    size_t i = (size_t)blockIdx.x * blockDim.x + threadIdx.x;
    if (i >= (size_t)rows * cols) return;
    int r = (int)(i / cols);
    int c = (int)(i % cols);
    dst[i] = __float2bfloat16(src[(size_t)r * srcld + srcoff + c]);
}

// ---------------- Wcat / bcat build ----------------
__global__ void wcat_kernel(const float* __restrict__ Wq, const float* __restrict__ Whh1)
{
    size_t i = (size_t)blockIdx.x * blockDim.x + threadIdx.x;
    if (i >= (size_t)QGH * HDIM) return;
    int rr = (int)(i / HDIM);
    int c  = (int)(i % HDIM);
    g_Wcat[i] = (rr < HDIM) ? Wq[(size_t)rr * HDIM + c]
                            : Whh1[(size_t)(rr - HDIM) * HDIM + c];
}
__global__ void bcat_kernel(const float* __restrict__ bq, const float* __restrict__ bhh1)
{
    int i = blockIdx.x * blockDim.x + threadIdx.x;
    if (i >= QGH) return;
    g_bcat[i] = (i < HDIM) ? bq[i] : bhh1[i - HDIM];
}

// ---------------- attention scores: scores[b,s] = wv . tanh(q[b] + kproj[b,s]) + bv ----------------
__global__ void attn_scores_kernel(const float* __restrict__ wv, const float* __restrict__ bv)
{
    const int s = blockIdx.x;
    const int b = blockIdx.y;
    const __nv_bfloat162* kp =
        reinterpret_cast<const __nv_bfloat162*>(&g_kprojb[((size_t)b * SDIM + s) * HDIM]);
    const float2* q2  = reinterpret_cast<const float2*>(&g_qgh1[(size_t)b * QGH]);
    const float2* wv2 = reinterpret_cast<const float2*>(wv);

    float sum = 0.0f;
    #pragma unroll
    for (int i = threadIdx.x; i < HDIM / 2; i += 128) {
        __nv_bfloat162 k = kp[i];
        float2 q = q2[i];
        float2 w = wv2[i];
        sum += fast_tanh(q.x + __low2float(k))  * w.x;
        sum += fast_tanh(q.y + __high2float(k)) * w.y;
    }
    sum = warpReduceSum(sum);
    __shared__ float sh[4];
    if ((threadIdx.x & 31) == 0) sh[threadIdx.x >> 5] = sum;
    __syncthreads();
    if (threadIdx.x == 0)
        g_attn[b * SDIM + s] = sh[0] + sh[1] + sh[2] + sh[3] + bv[0];
}

// ---------------- fused softmax + context: ctx[b] = softmax(scores[b]) @ enc_Y[b] ----------------
// grid (4, B), 256 threads; each block covers 256 h-columns
__global__ void ctx_softmax_kernel()
{
    const int b = blockIdx.y;
    const int tid = threadIdx.x;
    __shared__ float sc[SDIM];
    __shared__ float red[8];

    float v = (tid < SDIM) ? g_attn[b * SDIM + tid] : -1e30f;
    float m = warpReduceMax(v);
    if ((tid & 31) == 0) red[tid >> 5] = m;
    __syncthreads();
    m = red[0];
    #pragma unroll
    for (int w = 1; w < 8; w++) m = fmaxf(m, red[w]);

    float e = (tid < SDIM) ? __expf(v - m) : 0.0f;
    float s = warpReduceSum(e);
    __syncthreads();
    if ((tid & 31) == 0) red[tid >> 5] = s;
    __syncthreads();
    float tot = red[0];
    #pragma unroll
    for (int w = 1; w < 8; w++) tot += red[w];

    if (tid < SDIM) sc[tid] = e / tot;
    __syncthreads();

    const int h = blockIdx.x * 256 + tid;
    const bf16* ey = &g_encYb[(size_t)b * SDIM * HDIM + h];
    float acc = 0.0f;
    #pragma unroll 8
    for (int s2 = 0; s2 < SDIM; s2++)
        acc = fmaf(sc[s2], __bfloat162float(ey[(size_t)s2 * HDIM]), acc);
    g_ctx[b * HDIM + h] = acc;
}

// ---------------- GRU gate combine ----------------
__global__ void gru_gate_kernel(const float* __restrict__ gi, int ldgi,
                                const float* __restrict__ gh, int ldgh,
                                float* __restrict__ h, bf16* __restrict__ ysout)
{
    const int i = blockIdx.x * blockDim.x + threadIdx.x;   // [0, B*H)
    const int b = i >> 10;
    const int j = i & (HDIM - 1);
    const float* gib = gi + (size_t)b * ldgi;
    const float* ghb = gh + (size_t)b * ldgh;

    float r = fast_sigmoid(gib[j] + ghb[j]);
    float z = fast_sigmoid(gib[HDIM + j] + ghb[HDIM + j]);
    float n = fast_tanh(gib[2 * HDIM + j] + r * ghb[2 * HDIM + j]);
    float hn = (1.0f - z) * n + z * h[i];
    h[i] = hn;
    if (ysout) ysout[i] = __float2bfloat16(hn);
}

// ---------------- in-place log-softmax over V per output row ----------------
__global__ void logsoftmax_kernel(float* __restrict__ out)
{
    float* p = out + (size_t)blockIdx.x * VDIM;
    const int tid = threadIdx.x;

    float m = -1e30f;
    for (int v = tid; v < VDIM; v += 256) m = fmaxf(m, p[v]);
    m = warpReduceMax(m);
    __shared__ float shm[8];
    if ((tid & 31) == 0) shm[tid >> 5] = m;
    __syncthreads();
    m = shm[0];
    #pragma unroll
    for (int w = 1; w < 8; w++) m = fmaxf(m, shm[w]);

    float s = 0.0f;
    for (int v = tid; v < VDIM; v += 256) s += __expf(p[v] - m);
    s = warpReduceSum(s);
    __shared__ float shs[8];
    if ((tid & 31) == 0) shs[tid >> 5] = s;
    __syncthreads();
    s = shs[0];
    #pragma unroll
    for (int w = 1; w < 8; w++) s += shs[w];

    const float lse = m + logf(s);
    for (int v = tid; v < VDIM; v += 256) p[v] = p[v] - lse;
}

// ---------------- launcher ----------------
extern "C" void kernel_launch(void* const* d_in, const int* in_sizes, int n_in,
                              void* d_out, int out_size)
{
    (void)in_sizes; (void)n_in; (void)out_size;

    const int*   X     = (const int*)d_in[0];
    const float* encY  = (const float*)d_in[1];
    const float* h0in  = (const float*)d_in[2];
    const float* table = (const float*)d_in[3];
    const float* Wq    = (const float*)d_in[4];
    const float* bq    = (const float*)d_in[5];
    const float* Wk    = (const float*)d_in[6];
    const float* bk    = (const float*)d_in[7];
    const float* wv    = (const float*)d_in[8];
    const float* bv    = (const float*)d_in[9];
    const float* Wih0  = (const float*)d_in[10];
    const float* Whh0  = (const float*)d_in[11];
    const float* bih0  = (const float*)d_in[12];
    const float* bhh0  = (const float*)d_in[13];
    const float* Wih1  = (const float*)d_in[14];
    const float* Whh1  = (const float*)d_in[15];
    const float* bih1  = (const float*)d_in[16];
    const float* bhh1  = (const float*)d_in[17];
    const float* Wout  = (const float*)d_in[18];
    const float* bout  = (const float*)d_in[19];
    float* out = (float*)d_out;

    bf16 *kprojb, *encYb, *xsb, *Wihxb, *Wkb, *Woutb, *ysb;
    float *Xg, *h, *ctx, *gh0, *gi0, *gi1, *qgh1;
    cudaGetSymbolAddress((void**)&kprojb, g_kprojb);
    cudaGetSymbolAddress((void**)&encYb,  g_encYb);
    cudaGetSymbolAddress((void**)&xsb,    g_xsb);
    cudaGetSymbolAddress((void**)&Wihxb,  g_Wihxb);
    cudaGetSymbolAddress((void**)&Wkb,    g_Wkb);
    cudaGetSymbolAddress((void**)&Woutb,  g_Woutb);
    cudaGetSymbolAddress((void**)&ysb,    g_ysb);
    cudaGetSymbolAddress((void**)&Xg,     g_Xg);
    cudaGetSymbolAddress((void**)&h,      g_h);
    cudaGetSymbolAddress((void**)&ctx,    g_ctx);
    cudaGetSymbolAddress((void**)&gh0,    g_gh0);
    cudaGetSymbolAddress((void**)&gi0,    g_gi0);
    cudaGetSymbolAddress((void**)&gi1,    g_gi1);
    cudaGetSymbolAddress((void**)&qgh1,   g_qgh1);

    // ---- prologue: conversions + one-shot GEMMs ----
    {
        size_t n = (size_t)TDIM * BDIM * EDIM;
        gather_kernel<<<(unsigned)((n + 255) / 256), 256>>>(X, table);
    }
    {
        size_t n = (size_t)BDIM * SDIM * HDIM;
        f2bf_kernel<<<(unsigned)((n + 255) / 256), 256>>>(encY, encYb, n);
    }
    f2bf_kernel<<<(HDIM * HDIM + 255) / 256, 256>>>(Wk, Wkb, (size_t)HDIM * HDIM);
    {
        size_t n = (size_t)VDIM * HDIM;
        f2bf_kernel<<<(unsigned)((n + 255) / 256), 256>>>(Wout, Woutb, n);
    }
    // Wihx = Wih0[:, H:2H]  (x-part), bf16
    f2bf_strided_kernel<<<(G3H * HDIM + 255) / 256, 256>>>(Wih0, 2 * HDIM, HDIM,
                                                           Wihxb, G3H, HDIM);
    wcat_kernel<<<(QGH * HDIM + 255) / 256, 256>>>(Wq, Whh1);
    bcat_kernel<<<(QGH + 255) / 256, 256>>>(bq, bhh1);
    cudaMemcpyAsync(h, h0in, (size_t)2 * BDIM * HDIM * sizeof(float),
                    cudaMemcpyDeviceToDevice);

    // kproj (bf16 out): [B*S, H] = encY @ Wk^T + bk
    mma_gemm<bf16, false><<<dim3(HDIM / 128, (BDIM * SDIM) / 128), 256>>>(
        encYb, Wkb, bk, kprojb, BDIM * SDIM, HDIM, HDIM);
    // Xg: [T*B, 3H] = xs @ Wihx^T + bih0   (precomputed x-part of gi0, bias folded)
    mma_gemm<float, false><<<dim3(G3H / 128, (TDIM * BDIM) / 128), 256>>>(
        xsb, Wihxb, bih0, Xg, TDIM * BDIM, G3H, HDIM);

    float* h0p = h;                   // layer 0 hidden [B,H]
    float* h1p = h + BDIM * HDIM;     // layer 1 hidden [B,H]

    // ---- recurrent scan ----
    for (int t = 0; t < TDIM; t++) {
        // q|gh1 from old h1, gh0 from old h0 — one launch, 224 blocks
        stepstart_gemm<<<QGH / 32 + G3H / 32, 256>>>(h1p, h0p, Whh0, bhh0);
        attn_scores_kernel<<<dim3(SDIM, BDIM), 128>>>(wv, bv);
        ctx_softmax_kernel<<<dim3(4, BDIM), 256>>>();
        // gi0 = ctx @ Wih0[:, :H]^T + Xg[t]   (bias already inside Xg)
        sgemm_step<<<G3H / 32, 256>>>(ctx, Wih0, 2 * HDIM, nullptr,
                                      Xg + (size_t)t * BDIM * G3H, G3H,
                                      gi0, G3H, HDIM);
        gru_gate_kernel<<<(BDIM * HDIM) / 256, 256>>>(gi0, G3H, gh0, G3H, h0p, nullptr);
        // gi1 = h0_new @ Wih1^T + bih1
        sgemm_step<<<G3H / 32, 256>>>(h0p, Wih1, HDIM, bih1, nullptr, 0,
                                      gi1, G3H, HDIM);
        gru_gate_kernel<<<(BDIM * HDIM) / 256, 256>>>(gi1, G3H, qgh1 + HDIM, QGH, h1p,
                                                      ysb + (size_t)t * BDIM * HDIM);
    }

    // ---- logits (tensor core, ROWMAP into [B,T,V]) + log-softmax ----
    mma_gemm<float, true><<<dim3(VDIM / 128, (TDIM * BDIM) / 128), 256>>>(
        ysb, Woutb, bout, out, TDIM * BDIM, VDIM, HDIM);
    logsoftmax_kernel<<<BDIM * TDIM, 256>>>(out);
}

// round 4
// speedup vs baseline: 5.2420x; 2.3642x over previous
#include <cuda_runtime.h>
#include <cuda_bf16.h>
#include <cuda_fp16.h>
#include <math.h>

// Problem constants
#define BDIM 64
#define TDIM 64
#define SDIM 128
#define HDIM 1024
#define EDIM 1024
#define VDIM 32000
#define G3H  3072          // 3*H
#define QGH  4096          // q(1024) | gh1(3072)

typedef __nv_bfloat16 bf16;

// ---------------- scratch (static device globals; no allocation) ----------------
__device__ bf16  g_kprojb[(size_t)BDIM * SDIM * HDIM];   // [B,S,H] bf16
__device__ bf16  g_encYb [(size_t)BDIM * SDIM * HDIM];
__device__ bf16  g_xsb   [(size_t)TDIM * BDIM * EDIM];   // [T*B, E]
__device__ bf16  g_Wihxb [G3H * HDIM];                   // Wih0[:, H:2H]
__device__ bf16  g_Wih0cb[G3H * HDIM];                   // Wih0[:, 0:H]
__device__ bf16  g_Wih1b [G3H * HDIM];
__device__ bf16  g_Whh0b [G3H * HDIM];
__device__ bf16  g_Wcatb [QGH * HDIM];                   // [Wq; Whh1]
__device__ bf16  g_Wkb   [HDIM * HDIM];
__device__ bf16  g_Woutb [(size_t)VDIM * HDIM];
__device__ bf16  g_ysb   [(size_t)TDIM * BDIM * HDIM];
__device__ float g_Xg    [(size_t)TDIM * BDIM * G3H];    // x-part of gi0 (+bih0)
__device__ float g_bcat  [QGH];
__device__ float g_h     [2 * BDIM * HDIM];              // fp32 hidden
__device__ bf16  g_hb    [2 * BDIM * HDIM];              // bf16 mirror (GEMM A input)
__device__ float g_qgh1  [BDIM * QGH];                   // per-row: q | gh1
__device__ float g_attn  [BDIM * SDIM];
__device__ bf16  g_ctxb  [BDIM * HDIM];
__device__ float g_gh0   [BDIM * G3H];
__device__ float g_gi0   [BDIM * G3H];
__device__ float g_gi1   [BDIM * G3H];

// ---------------- helpers ----------------
__device__ __forceinline__ float fast_tanh(float x) {
    float y; asm("tanh.approx.f32 %0, %1;" : "=f"(y) : "f"(x)); return y;
}
__device__ __forceinline__ float fast_sigmoid(float x) {
    return 1.0f / (1.0f + __expf(-x));
}
__device__ __forceinline__ float warpReduceSum(float v) {
    #pragma unroll
    for (int o = 16; o > 0; o >>= 1) v += __shfl_xor_sync(0xffffffffu, v, o);
    return v;
}
__device__ __forceinline__ float warpReduceMax(float v) {
    #pragma unroll
    for (int o = 16; o > 0; o >>= 1) v = fmaxf(v, __shfl_xor_sync(0xffffffffu, v, o));
    return v;
}

__device__ __forceinline__ void mma16816(float* d, const unsigned* a, const unsigned* b) {
    asm volatile(
        "mma.sync.aligned.m16n8k16.row.col.f32.bf16.bf16.f32 "
        "{%0,%1,%2,%3},{%4,%5,%6,%7},{%8,%9},{%0,%1,%2,%3};"
        : "+f"(d[0]), "+f"(d[1]), "+f"(d[2]), "+f"(d[3])
        : "r"(a[0]), "r"(a[1]), "r"(a[2]), "r"(a[3]), "r"(b[0]), "r"(b[1]));
}

#define CPASYNC16(dst_u32, src_ptr) \
    asm volatile("cp.async.cg.shared.global [%0], [%1], 16;" :: "r"(dst_u32), "l"(src_ptr))
#define CPCOMMIT() asm volatile("cp.async.commit_group;")
#define CPWAIT(n)  asm volatile("cp.async.wait_group %0;" :: "n"(n))

template <typename T> __device__ __forceinline__ T toOut(float v);
template <> __device__ __forceinline__ float toOut<float>(float v) { return v; }
template <> __device__ __forceinline__ bf16  toOut<bf16 >(float v) { return __float2bfloat16(v); }

// ============ big bf16 tensor-core GEMM (cp.async double-buffered) ============
// C[M,N] = A[M,K] @ B[N,K]^T + bias. ROWMAP: out row g=t*64+b -> stored row b*64+t.
// M%128==0, N%128==0, K%32==0.
template <typename OutT, bool ROWMAP>
__global__ __launch_bounds__(256)
void mma_gemm(const bf16* __restrict__ A, const bf16* __restrict__ B,
              const float* __restrict__ bias, OutT* __restrict__ C,
              int M, int N, int K)
{
    constexpr int BM = 128, BN = 128, BK = 32, PAD = 8;
    __shared__ __align__(16) bf16 As[2][BM][BK + PAD];
    __shared__ __align__(16) bf16 Bs[2][BN][BK + PAD];

    const int bm = blockIdx.y * BM;
    const int bn = blockIdx.x * BN;
    const int tid = threadIdx.x;
    const int lane = tid & 31;
    const int warp = tid >> 5;
    const int wm = (warp >> 2) * 64;
    const int wn = (warp & 3) * 32;

    float acc[4][4][4];
    #pragma unroll
    for (int i = 0; i < 4; i++)
        #pragma unroll
        for (int j = 0; j < 4; j++)
            #pragma unroll
            for (int x = 0; x < 4; x++) acc[i][j][x] = 0.0f;

    const int r  = lane >> 2;
    const int c2 = (lane & 3) * 2;

    const int lrow = tid >> 1;               // 0..127
    const int lc8  = (tid & 1) * 16;         // 0 or 16 (two 16B chunks per row-half)
    // each thread loads 2x16B for A and 2x16B for B per stage:
    // rows lrow (chunk lc8) and lrow (chunk lc8+? ) -> use pattern: 512 chunks/matrix,
    // 256 threads -> 2 chunks each: (tid, tid+256)
    auto load_stage = [&](int s, int k0) {
        #pragma unroll
        for (int v = 0; v < 2; v++) {
            int idx = tid + v * 256;         // 0..511
            int row = idx >> 2;              // 0..127
            int c8  = (idx & 3) * 8;         // 0,8,16,24 (bf16 elems)
            unsigned da = (unsigned)__cvta_generic_to_shared(&As[s][row][c8]);
            CPASYNC16(da, &A[(size_t)(bm + row) * K + k0 + c8]);
            unsigned db = (unsigned)__cvta_generic_to_shared(&Bs[s][row][c8]);
            CPASYNC16(db, &B[(size_t)(bn + row) * K + k0 + c8]);
        }
        CPCOMMIT();
    };
    (void)lrow; (void)lc8;

    const int NIT = K / BK;
    load_stage(0, 0);

    for (int it = 0; it < NIT; it++) {
        if (it + 1 < NIT) load_stage((it + 1) & 1, (it + 1) * BK);
        if (it + 1 < NIT) { CPWAIT(1); } else { CPWAIT(0); }
        __syncthreads();
        const int s = it & 1;

        #pragma unroll
        for (int ks = 0; ks < 2; ks++) {
            unsigned a[4][4], b[4][2];
            #pragma unroll
            for (int i = 0; i < 4; i++) {
                int mr = wm + i * 16;
                a[i][0] = *reinterpret_cast<const unsigned*>(&As[s][mr + r    ][ks * 16 + c2    ]);
                a[i][1] = *reinterpret_cast<const unsigned*>(&As[s][mr + r + 8][ks * 16 + c2    ]);
                a[i][2] = *reinterpret_cast<const unsigned*>(&As[s][mr + r    ][ks * 16 + c2 + 8]);
                a[i][3] = *reinterpret_cast<const unsigned*>(&As[s][mr + r + 8][ks * 16 + c2 + 8]);
            }
            #pragma unroll
            for (int j = 0; j < 4; j++) {
                int nr = wn + j * 8 + r;
                b[j][0] = *reinterpret_cast<const unsigned*>(&Bs[s][nr][ks * 16 + c2    ]);
                b[j][1] = *reinterpret_cast<const unsigned*>(&Bs[s][nr][ks * 16 + c2 + 8]);
            }
            #pragma unroll
            for (int i = 0; i < 4; i++)
                #pragma unroll
                for (int j = 0; j < 4; j++)
                    mma16816(acc[i][j], a[i], b[j]);
        }
        __syncthreads();
    }

    #pragma unroll
    for (int i = 0; i < 4; i++) {
        int grow0 = bm + wm + i * 16 + r;
        #pragma unroll
        for (int half = 0; half < 2; half++) {
            int g = grow0 + half * 8;
            size_t rowBase;
            if (ROWMAP) {
                int b_ = g & (BDIM - 1);
                int t_ = g >> 6;
                rowBase = (size_t)(b_ * TDIM + t_) * N;
            } else {
                rowBase = (size_t)g * N;
            }
            #pragma unroll
            for (int j = 0; j < 4; j++) {
                int col = bn + wn + j * 8 + c2;
                float b0 = bias ? bias[col]     : 0.0f;
                float b1 = bias ? bias[col + 1] : 0.0f;
                C[rowBase + col    ] = toOut<OutT>(acc[i][j][half * 2    ] + b0);
                C[rowBase + col + 1] = toOut<OutT>(acc[i][j][half * 2 + 1] + b1);
            }
        }
    }
}

// ============ small bf16 mma GEMM for the recurrence: C[64, 32-col slab] ============
// A[64,K] bf16, W[N,K] bf16 (rows bn..bn+31), optional bias[N] fp32, addend P, out fp32.
__device__ __forceinline__ void stepmma_body(
    const bf16* __restrict__ A, const bf16* __restrict__ W,
    const float* __restrict__ bias, const float* __restrict__ P, int ldp,
    float* __restrict__ C, int ldc, int bn, int K)
{
    constexpr int BK = 32, PAD = 8;
    __shared__ __align__(16) bf16 As[64][BK + PAD];
    __shared__ __align__(16) bf16 Ws[32][BK + PAD];

    const int tid = threadIdx.x;
    const int lane = tid & 31;
    const int warp = tid >> 5;             // 8 warps: 4 (M) x 2 (N)
    const int wm = (warp >> 1) * 16;
    const int wn = (warp & 1) * 16;
    const int r  = lane >> 2;
    const int c2 = (lane & 3) * 2;

    float acc[2][4];
    #pragma unroll
    for (int j = 0; j < 2; j++)
        #pragma unroll
        for (int x = 0; x < 4; x++) acc[j][x] = 0.0f;

    for (int k0 = 0; k0 < K; k0 += BK) {
        {   // A: 64 rows x 32 cols = 256 x 16B, 256 threads
            int row = tid >> 2, c8 = (tid & 3) * 8;
            *reinterpret_cast<uint4*>(&As[row][c8]) =
                *reinterpret_cast<const uint4*>(&A[(size_t)row * K + k0 + c8]);
        }
        if (tid < 128) {   // W: 32 rows x 32 cols = 128 x 16B
            int row = tid >> 2, c8 = (tid & 3) * 8;
            *reinterpret_cast<uint4*>(&Ws[row][c8]) =
                *reinterpret_cast<const uint4*>(&W[(size_t)(bn + row) * K + k0 + c8]);
        }
        __syncthreads();

        #pragma unroll
        for (int ks = 0; ks < 2; ks++) {
            unsigned a[4], b[2][2];
            a[0] = *reinterpret_cast<const unsigned*>(&As[wm + r    ][ks * 16 + c2    ]);
            a[1] = *reinterpret_cast<const unsigned*>(&As[wm + r + 8][ks * 16 + c2    ]);
            a[2] = *reinterpret_cast<const unsigned*>(&As[wm + r    ][ks * 16 + c2 + 8]);
            a[3] = *reinterpret_cast<const unsigned*>(&As[wm + r + 8][ks * 16 + c2 + 8]);
            #pragma unroll
            for (int j = 0; j < 2; j++) {
                int nr = wn + j * 8 + r;
                b[j][0] = *reinterpret_cast<const unsigned*>(&Ws[nr][ks * 16 + c2    ]);
                b[j][1] = *reinterpret_cast<const unsigned*>(&Ws[nr][ks * 16 + c2 + 8]);
            }
            mma16816(acc[0], a, b[0]);
            mma16816(acc[1], a, b[1]);
        }
        __syncthreads();
    }

    #pragma unroll
    for (int j = 0; j < 2; j++) {
        #pragma unroll
        for (int half = 0; half < 2; half++) {
            int row = wm + r + half * 8;
            int col = bn + wn + j * 8 + c2;
            float v0 = acc[j][half * 2    ];
            float v1 = acc[j][half * 2 + 1];
            if (bias) { v0 += bias[col]; v1 += bias[col + 1]; }
            if (P)    { v0 += P[(size_t)row * ldp + col]; v1 += P[(size_t)row * ldp + col + 1]; }
            C[(size_t)row * ldc + col    ] = v0;
            C[(size_t)row * ldc + col + 1] = v1;
        }
    }
}

// fused step-start: [q|gh1] = h1 @ Wcat^T + bcat  (128 blocks), gh0 = h0 @ Whh0^T + bhh0 (96)
__global__ __launch_bounds__(256)
void step_start_kernel(const float* __restrict__ bhh0)
{
    const bf16* h0b = g_hb;
    const bf16* h1b = g_hb + BDIM * HDIM;
    if (blockIdx.x < QGH / 32)
        stepmma_body(h1b, g_Wcatb, g_bcat, nullptr, 0, g_qgh1, QGH, blockIdx.x * 32, HDIM);
    else
        stepmma_body(h0b, g_Whh0b, bhh0, nullptr, 0, g_gh0, G3H,
                     (blockIdx.x - QGH / 32) * 32, HDIM);
}

// generic 64xN step GEMM (N=3072, 96 blocks)
__global__ __launch_bounds__(256)
void step_gemm_kernel(const bf16* __restrict__ A, const bf16* __restrict__ W,
                      const float* __restrict__ bias, const float* __restrict__ P,
                      float* __restrict__ C)
{
    stepmma_body(A, W, bias, P, G3H, C, G3H, blockIdx.x * 32, HDIM);
}

// ---------------- embedding gather -> bf16 (one block per (t,b) row) ----------------
__global__ void gather_kernel(const int* __restrict__ X, const float* __restrict__ table)
{
    const int tb = blockIdx.x;                 // t*64+b
    const int b = tb & (BDIM - 1);
    const int t = tb >> 6;
    const float4* src = reinterpret_cast<const float4*>(
        &table[(size_t)X[b * TDIM + t] * EDIM]);
    float4 f = src[threadIdx.x];
    bf16* dst = &g_xsb[(size_t)tb * EDIM + threadIdx.x * 4];
    dst[0] = __float2bfloat16(f.x);
    dst[1] = __float2bfloat16(f.y);
    dst[2] = __float2bfloat16(f.z);
    dst[3] = __float2bfloat16(f.w);
}

// ---------------- vectorized fp32 -> bf16 (n % 4 == 0) ----------------
__global__ void f2bf4_kernel(const float* __restrict__ src, bf16* __restrict__ dst, size_t n4)
{
    size_t i = (size_t)blockIdx.x * blockDim.x + threadIdx.x;
    if (i >= n4) return;
    float4 f = reinterpret_cast<const float4*>(src)[i];
    __nv_bfloat162 lo = __floats2bfloat162_rn(f.x, f.y);
    __nv_bfloat162 hi = __floats2bfloat162_rn(f.z, f.w);
    reinterpret_cast<__nv_bfloat162*>(dst)[i * 2    ] = lo;
    reinterpret_cast<__nv_bfloat162*>(dst)[i * 2 + 1] = hi;
}
// strided: dst[r*cols+c] = src[r*srcld + srcoff + c], cols % 4 == 0
__global__ void f2bf4_strided_kernel(const float* __restrict__ src, int srcld, int srcoff,
                                     bf16* __restrict__ dst, int rows, int cols)
{
    size_t i = (size_t)blockIdx.x * blockDim.x + threadIdx.x;   // vec4 index
    size_t n4 = (size_t)rows * cols / 4;
    if (i >= n4) return;
    int cpr = cols / 4;
    int r = (int)(i / cpr);
    int c4 = (int)(i % cpr);
    float4 f = *reinterpret_cast<const float4*>(&src[(size_t)r * srcld + srcoff + c4 * 4]);
    __nv_bfloat162 lo = __floats2bfloat162_rn(f.x, f.y);
    __nv_bfloat162 hi = __floats2bfloat162_rn(f.z, f.w);
    __nv_bfloat162* d = reinterpret_cast<__nv_bfloat162*>(&dst[(size_t)r * cols + c4 * 4]);
    d[0] = lo; d[1] = hi;
}

// ---------------- Wcat (bf16) / bcat build ----------------
__global__ void wcatb_kernel(const float* __restrict__ Wq, const float* __restrict__ Whh1)
{
    size_t i = (size_t)blockIdx.x * blockDim.x + threadIdx.x;   // vec4
    size_t n4 = (size_t)QGH * HDIM / 4;
    if (i >= n4) return;
    size_t e = i * 4;
    int rr = (int)(e / HDIM);
    int c  = (int)(e % HDIM);
    const float* s = (rr < HDIM) ? &Wq[(size_t)rr * HDIM + c]
                                 : &Whh1[(size_t)(rr - HDIM) * HDIM + c];
    float4 f = *reinterpret_cast<const float4*>(s);
    __nv_bfloat162* d = reinterpret_cast<__nv_bfloat162*>(&g_Wcatb[e]);
    d[0] = __floats2bfloat162_rn(f.x, f.y);
    d[1] = __floats2bfloat162_rn(f.z, f.w);
}
__global__ void bcat_kernel(const float* __restrict__ bq, const float* __restrict__ bhh1)
{
    int i = blockIdx.x * blockDim.x + threadIdx.x;
    if (i >= QGH) return;
    g_bcat[i] = (i < HDIM) ? bq[i] : bhh1[i - HDIM];
}

// ---------------- init hidden: fp32 copy + bf16 mirror ----------------
__global__ void hinit_kernel(const float* __restrict__ h0in)
{
    int i = blockIdx.x * blockDim.x + threadIdx.x;
    if (i >= 2 * BDIM * HDIM) return;
    float v = h0in[i];
    g_h[i]  = v;
    g_hb[i] = __float2bfloat16(v);
}

// ---------------- attention scores (f16x2 tanh): scores[b,s] = wv . tanh(q[b]+kproj[b,s]) + bv
__global__ void attn_scores_kernel(const float* __restrict__ wv, const float* __restrict__ bv)
{
    const int s = blockIdx.x;
    const int b = blockIdx.y;
    const __nv_bfloat162* kp =
        reinterpret_cast<const __nv_bfloat162*>(&g_kprojb[((size_t)b * SDIM + s) * HDIM]);
    const float2* q2  = reinterpret_cast<const float2*>(&g_qgh1[(size_t)b * QGH]);
    const float2* wv2 = reinterpret_cast<const float2*>(wv);

    float sum = 0.0f;
    #pragma unroll 4
    for (int i = threadIdx.x; i < HDIM / 2; i += 128) {
        __nv_bfloat162 k = kp[i];
        float2 q = q2[i];
        float2 w = wv2[i];
        float x0 = q.x + __low2float(k);
        float x1 = q.y + __high2float(k);
        __half2 hx = __floats2half2_rn(x0, x1);
        unsigned hin = *reinterpret_cast<unsigned*>(&hx);
        unsigned hout;
        asm("tanh.approx.f16x2 %0, %1;" : "=r"(hout) : "r"(hin));
        __half2 ht = *reinterpret_cast<__half2*>(&hout);
        float2 tv = __half22float2(ht);
        sum += tv.x * w.x + tv.y * w.y;
    }
    sum = warpReduceSum(sum);
    __shared__ float sh[4];
    if ((threadIdx.x & 31) == 0) sh[threadIdx.x >> 5] = sum;
    __syncthreads();
    if (threadIdx.x == 0)
        g_attn[b * SDIM + s] = sh[0] + sh[1] + sh[2] + sh[3] + bv[0];
}

// ---------------- fused softmax + context (bf16 out) ----------------
__global__ void ctx_softmax_kernel()
{
    const int b = blockIdx.y;
    const int tid = threadIdx.x;
    __shared__ float sc[SDIM];
    __shared__ float red[8];

    float v = (tid < SDIM) ? g_attn[b * SDIM + tid] : -1e30f;
    float m = warpReduceMax(v);
    if ((tid & 31) == 0) red[tid >> 5] = m;
    __syncthreads();
    m = red[0];
    #pragma unroll
    for (int w = 1; w < 8; w++) m = fmaxf(m, red[w]);

    float e = (tid < SDIM) ? __expf(v - m) : 0.0f;
    float s = warpReduceSum(e);
    __syncthreads();
    if ((tid & 31) == 0) red[tid >> 5] = s;
    __syncthreads();
    float tot = red[0];
    #pragma unroll
    for (int w = 1; w < 8; w++) tot += red[w];

    if (tid < SDIM) sc[tid] = e / tot;
    __syncthreads();

    const int h = blockIdx.x * 256 + tid;
    const bf16* ey = &g_encYb[(size_t)b * SDIM * HDIM + h];
    float acc = 0.0f;
    #pragma unroll 8
    for (int s2 = 0; s2 < SDIM; s2++)
        acc = fmaf(sc[s2], __bfloat162float(ey[(size_t)s2 * HDIM]), acc);
    g_ctxb[b * HDIM + h] = __float2bfloat16(acc);
}

// ---------------- GRU gate combine: fp32 h + bf16 mirror (+ optional ys bf16) --------
__global__ void gru_gate_kernel(const float* __restrict__ gi, int ldgi,
                                const float* __restrict__ gh, int ldgh,
                                float* __restrict__ h, bf16* __restrict__ hb,
                                bf16* __restrict__ ysout)
{
    const int i = blockIdx.x * blockDim.x + threadIdx.x;   // [0, B*H)
    const int b = i >> 10;
    const int j = i & (HDIM - 1);
    const float* gib = gi + (size_t)b * ldgi;
    const float* ghb = gh + (size_t)b * ldgh;

    float r = fast_sigmoid(gib[j] + ghb[j]);
    float z = fast_sigmoid(gib[HDIM + j] + ghb[HDIM + j]);
    float n = fast_tanh(gib[2 * HDIM + j] + r * ghb[2 * HDIM + j]);
    float hn = (1.0f - z) * n + z * h[i];
    h[i]  = hn;
    hb[i] = __float2bfloat16(hn);
    if (ysout) ysout[i] = __float2bfloat16(hn);
}

// ---------------- in-place log-softmax over V (vectorized) ----------------
__global__ void logsoftmax_kernel(float* __restrict__ out)
{
    float4* p4 = reinterpret_cast<float4*>(out + (size_t)blockIdx.x * VDIM);
    const int n4 = VDIM / 4;       // 8000
    const int tid = threadIdx.x;

    float m = -1e30f;
    for (int v = tid; v < n4; v += 256) {
        float4 f = p4[v];
        m = fmaxf(m, fmaxf(fmaxf(f.x, f.y), fmaxf(f.z, f.w)));
    }
    m = warpReduceMax(m);
    __shared__ float shm[8];
    if ((tid & 31) == 0) shm[tid >> 5] = m;
    __syncthreads();
    m = shm[0];
    #pragma unroll
    for (int w = 1; w < 8; w++) m = fmaxf(m, shm[w]);

    float s = 0.0f;
    for (int v = tid; v < n4; v += 256) {
        float4 f = p4[v];
        s += __expf(f.x - m) + __expf(f.y - m) + __expf(f.z - m) + __expf(f.w - m);
    }
    s = warpReduceSum(s);
    __shared__ float shs[8];
    if ((tid & 31) == 0) shs[tid >> 5] = s;
    __syncthreads();
    s = shs[0];
    #pragma unroll
    for (int w = 1; w < 8; w++) s += shs[w];

    const float lse = m + logf(s);
    for (int v = tid; v < n4; v += 256) {
        float4 f = p4[v];
        f.x -= lse; f.y -= lse; f.z -= lse; f.w -= lse;
        p4[v] = f;
    }
}

// ---------------- launcher ----------------
extern "C" void kernel_launch(void* const* d_in, const int* in_sizes, int n_in,
                              void* d_out, int out_size)
{
    (void)in_sizes; (void)n_in; (void)out_size;

    const int*   X     = (const int*)d_in[0];
    const float* encY  = (const float*)d_in[1];
    const float* h0in  = (const float*)d_in[2];
    const float* table = (const float*)d_in[3];
    const float* Wq    = (const float*)d_in[4];
    const float* bq    = (const float*)d_in[5];
    const float* Wk    = (const float*)d_in[6];
    const float* bk    = (const float*)d_in[7];
    const float* wv    = (const float*)d_in[8];
    const float* bv    = (const float*)d_in[9];
    const float* Wih0  = (const float*)d_in[10];
    const float* Whh0  = (const float*)d_in[11];
    const float* bih0  = (const float*)d_in[12];
    const float* bhh0  = (const float*)d_in[13];
    const float* Wih1  = (const float*)d_in[14];
    const float* Whh1  = (const float*)d_in[15];
    const float* bih1  = (const float*)d_in[16];
    const float* bhh1  = (const float*)d_in[17];
    const float* Wout  = (const float*)d_in[18];
    const float* bout  = (const float*)d_in[19];
    float* out = (float*)d_out;

    bf16 *kprojb, *encYb, *xsb, *Wihxb, *Wih0cb, *Wih1b, *Woutb, *Wkb, *ysb, *hb, *ctxb;
    float *Xg, *h, *gh0, *gi0, *gi1, *qgh1;
    cudaGetSymbolAddress((void**)&kprojb, g_kprojb);
    cudaGetSymbolAddress((void**)&encYb,  g_encYb);
    cudaGetSymbolAddress((void**)&xsb,    g_xsb);
    cudaGetSymbolAddress((void**)&Wihxb,  g_Wihxb);
    cudaGetSymbolAddress((void**)&Wih0cb, g_Wih0cb);
    cudaGetSymbolAddress((void**)&Wih1b,  g_Wih1b);
    cudaGetSymbolAddress((void**)&Woutb,  g_Woutb);
    cudaGetSymbolAddress((void**)&Wkb,    g_Wkb);
    cudaGetSymbolAddress((void**)&ysb,    g_ysb);
    cudaGetSymbolAddress((void**)&hb,     g_hb);
    cudaGetSymbolAddress((void**)&ctxb,   g_ctxb);
    cudaGetSymbolAddress((void**)&Xg,     g_Xg);
    cudaGetSymbolAddress((void**)&h,      g_h);
    cudaGetSymbolAddress((void**)&gh0,    g_gh0);
    cudaGetSymbolAddress((void**)&gi0,    g_gi0);
    cudaGetSymbolAddress((void**)&gi1,    g_gi1);
    cudaGetSymbolAddress((void**)&qgh1,   g_qgh1);

    // ---- prologue: conversions ----
    gather_kernel<<<TDIM * BDIM, 256>>>(X, table);
    {
        size_t n4 = (size_t)BDIM * SDIM * HDIM / 4;
        f2bf4_kernel<<<(unsigned)((n4 + 255) / 256), 256>>>(encY, encYb, n4);
    }
    f2bf4_kernel<<<(HDIM * HDIM / 4 + 255) / 256, 256>>>(Wk, Wkb, (size_t)HDIM * HDIM / 4);
    {
        size_t n4 = (size_t)VDIM * HDIM / 4;
        f2bf4_kernel<<<(unsigned)((n4 + 255) / 256), 256>>>(Wout, Woutb, n4);
    }
    f2bf4_strided_kernel<<<(G3H * HDIM / 4 + 255) / 256, 256>>>(Wih0, 2 * HDIM, HDIM,
                                                                Wihxb, G3H, HDIM);
    f2bf4_strided_kernel<<<(G3H * HDIM / 4 + 255) / 256, 256>>>(Wih0, 2 * HDIM, 0,
                                                                Wih0cb, G3H, HDIM);
    {
        bf16* Whh0b; cudaGetSymbolAddress((void**)&Whh0b, g_Whh0b);
        f2bf4_kernel<<<(G3H * HDIM / 4 + 255) / 256, 256>>>(Whh0, Whh0b,
                                                            (size_t)G3H * HDIM / 4);
        f2bf4_kernel<<<(G3H * HDIM / 4 + 255) / 256, 256>>>(Wih1, Wih1b,
                                                            (size_t)G3H * HDIM / 4);
    }
    wcatb_kernel<<<(QGH * HDIM / 4 + 255) / 256, 256>>>(Wq, Whh1);
    bcat_kernel<<<(QGH + 255) / 256, 256>>>(bq, bhh1);
    hinit_kernel<<<(2 * BDIM * HDIM + 255) / 256, 256>>>(h0in);

    // kproj (bf16 out), Xg (fp32, bih0 folded)
    mma_gemm<bf16, false><<<dim3(HDIM / 128, (BDIM * SDIM) / 128), 256>>>(
        encYb, Wkb, bk, kprojb, BDIM * SDIM, HDIM, HDIM);
    mma_gemm<float, false><<<dim3(G3H / 128, (TDIM * BDIM) / 128), 256>>>(
        xsb, Wihxb, bih0, Xg, TDIM * BDIM, G3H, HDIM);

    float* h0p = h;
    float* h1p = h + BDIM * HDIM;
    bf16*  h0b = hb;

    // ---- recurrent scan ----
    for (int t = 0; t < TDIM; t++) {
        step_start_kernel<<<QGH / 32 + G3H / 32, 256>>>(bhh0);
        attn_scores_kernel<<<dim3(SDIM, BDIM), 128>>>(wv, bv);
        ctx_softmax_kernel<<<dim3(4, BDIM), 256>>>();
        // gi0 = ctx @ Wih0c^T + Xg[t]
        step_gemm_kernel<<<G3H / 32, 256>>>(ctxb, Wih0cb, nullptr,
                                            Xg + (size_t)t * BDIM * G3H, gi0);
        gru_gate_kernel<<<(BDIM * HDIM) / 256, 256>>>(gi0, G3H, gh0, G3H,
                                                      h0p, hb, nullptr);
        // gi1 = h0_new @ Wih1^T + bih1
        step_gemm_kernel<<<G3H / 32, 256>>>(h0b, Wih1b, bih1, nullptr, gi1);
        gru_gate_kernel<<<(BDIM * HDIM) / 256, 256>>>(gi1, G3H, qgh1 + HDIM, QGH,
                                                      h1p, hb + BDIM * HDIM,
                                                      ysb + (size_t)t * BDIM * HDIM);
    }

    // ---- logits (tensor core, ROWMAP into [B,T,V]) + log-softmax ----
    mma_gemm<float, true><<<dim3(VDIM / 128, (TDIM * BDIM) / 128), 256>>>(
        ysb, Woutb, bout, out, TDIM * BDIM, VDIM, HDIM);
    logsoftmax_kernel<<<BDIM * TDIM, 256>>>(out);
}